// round 11
// baseline (speedup 1.0000x reference)
#include <cuda_runtime.h>
#include <cuda_bf16.h>

// img : (1, 64, 64, 1024) float32, NHWC
// rois: (1, 512, 4) int32  -> (x, y, w, h)
// out : (1, 512, 7, 7, 1024) float32
#define POOL   7
#define NROIS  512
#define IMG_W  64

typedef unsigned long long u64t;

// ---- packed f32x2 helpers (sm_103a) ----
__device__ __forceinline__ u64t pk(float v) {
    u64t r;
    asm("mov.b64 %0, {%1, %1};" : "=l"(r) : "f"(v));
    return r;
}
__device__ __forceinline__ u64t sub2(u64t a, u64t b) {
    u64t r;
    asm("sub.rn.f32x2 %0, %1, %2;" : "=l"(r) : "l"(a), "l"(b));
    return r;
}
__device__ __forceinline__ u64t fma2(u64t a, u64t b, u64t c) {
    u64t r;
    asm("fma.rn.f32x2 %0, %1, %2, %3;" : "=l"(r) : "l"(a), "l"(b), "l"(c));
    return r;
}

// Bilinear lerp in packed f32x2: 3 sub + 3 fma, only FX/FY packed constants.
__device__ __forceinline__ u64t blend1(u64t v00, u64t v01, u64t v10, u64t v11,
                                       u64t FX, u64t FY) {
    const u64t top = fma2(sub2(v01, v00), FX, v00);
    const u64t bot = fma2(sub2(v11, v10), FX, v10);
    return fma2(sub2(bot, top), FY, top);
}

// One CTA per (roi, py) output row: 7 px cells, 512 threads, one b64 (float2)
// lane each. LDG.64 halves the wavefronts-per-load-burst vs LDG.128 (queue
// model: lat = Q_at_issue + nL), doubling warp count per CTA at lower regs.
// Depth-1 software pipeline over px: 4 independent 8B loads in flight per
// thread while blending the previous cell.
__global__ __launch_bounds__(512)
void roi_pool_kernel(const float* __restrict__ img,
                     const int*   __restrict__ rois,
                     float*       __restrict__ out)
{
    const int bid = blockIdx.x;           // roi*7 + py
    const int roi = bid / POOL;
    const int py  = bid - roi * POOL;

    const int4 r = __ldg(((const int4*)rois) + roi);   // x, y, w, h

    // Loop-invariant y-axis work (match reference fp32 arithmetic exactly)
    const float stepx = (float)r.z / (float)POOL;
    const float sy = (float)py * ((float)r.w / (float)POOL);
    const int   y0 = (int)sy;
    const float fy = sy - (float)y0;
    const int   y1 = min(y0 + 1, r.w - 1);
    const int   wm1 = r.z - 1;

    const u64t FY = pk(fy);

    const int c = threadIdx.x;            // 0..511 b64 lane
    const u64t* ibase = (const u64t*)img; // 8B units; pixel = 512 lanes
    const unsigned row0 = (unsigned)((r.y + y0) * IMG_W + r.x) * 512u + c;
    const unsigned row1 = (unsigned)((r.y + y1) * IMG_W + r.x) * 512u + c;

    u64t* optr = (u64t*)out + ((size_t)bid * POOL) * 512 + c;

    // ---- prologue: px = 0 (sx = 0, x0 = 0, fx = 0) ----
    float fxc = 0.0f;
    {
        const unsigned x1u = (unsigned)min(1, wm1) * 512u;
        u64t a00 = __ldg(ibase + row0);
        u64t a01 = __ldg(ibase + row0 + x1u);
        u64t a10 = __ldg(ibase + row1);
        u64t a11 = __ldg(ibase + row1 + x1u);

        #pragma unroll
        for (int px = 1; px < POOL; ++px) {
            const float sx  = (float)px * stepx;
            const int   x0  = (int)sx;
            const float fxn = sx - (float)x0;
            const unsigned u0 = (unsigned)x0 * 512u;
            const unsigned u1 = (unsigned)min(x0 + 1, wm1) * 512u;

            // prefetch next cell's four pixels before consuming current regs
            const u64t b00 = __ldg(ibase + row0 + u0);
            const u64t b01 = __ldg(ibase + row0 + u1);
            const u64t b10 = __ldg(ibase + row1 + u0);
            const u64t b11 = __ldg(ibase + row1 + u1);

            *optr = blend1(a00, a01, a10, a11, pk(fxc), FY);
            optr += 512;

            a00 = b00; a01 = b01; a10 = b10; a11 = b11;
            fxc = fxn;
        }

        // ---- epilogue: px = 6 ----
        *optr = blend1(a00, a01, a10, a11, pk(fxc), FY);
    }
}

extern "C" void kernel_launch(void* const* d_in, const int* in_sizes, int n_in,
                              void* d_out, int out_size)
{
    const float* img  = (const float*)d_in[0];
    const int*   rois = (const int*)d_in[1];
    float*       out  = (float*)d_out;

    const int grid = NROIS * POOL;        // 3584 CTAs, one per (roi, py)
    roi_pool_kernel<<<grid, 512>>>(img, rois, out);
}

// round 12
// speedup vs baseline: 1.1830x; 1.1830x over previous
#include <cuda_runtime.h>
#include <cuda_bf16.h>

// img : (1, 64, 64, 1024) float32, NHWC
// rois: (1, 512, 4) int32  -> (x, y, w, h)
// out : (1, 512, 7, 7, 1024) float32
#define POOL   7
#define NROIS  512
#define IMG_W  64

typedef unsigned long long u64t;

// ---- packed f32x2 helpers (sm_103a) ----
__device__ __forceinline__ u64t pk(float v) {
    u64t r;
    asm("mov.b64 %0, {%1, %1};" : "=l"(r) : "f"(v));
    return r;
}
__device__ __forceinline__ u64t mul2(u64t a, u64t b) {
    u64t r;
    asm("mul.rn.f32x2 %0, %1, %2;" : "=l"(r) : "l"(a), "l"(b));
    return r;
}
__device__ __forceinline__ u64t fma2(u64t a, u64t b, u64t c) {
    u64t r;
    asm("fma.rn.f32x2 %0, %1, %2, %3;" : "=l"(r) : "l"(a), "l"(b), "l"(c));
    return r;
}

// 16B streaming store (output never re-read) — don't pollute L1.
__device__ __forceinline__ void stg_cs(ulonglong2* p, ulonglong2 v) {
    asm volatile("st.global.cs.v2.b64 [%0], {%1, %2};"
                 :: "l"(p), "l"(v.x), "l"(v.y) : "memory");
}

__device__ __forceinline__ ulonglong2 blend2(ulonglong2 v00, ulonglong2 v01,
                                             ulonglong2 v10, ulonglong2 v11,
                                             float fx, float fy) {
    const float w11 = fx * fy;
    const float w01 = fx - w11;          // fx*(1-fy)
    const float w10 = fy - w11;          // (1-fx)*fy
    const float w00 = 1.0f - fx - w10;   // (1-fx)*(1-fy)
    const u64t W00 = pk(w00), W01 = pk(w01), W10 = pk(w10), W11 = pk(w11);
    ulonglong2 o;
    o.x = fma2(v11.x, W11, fma2(v10.x, W10, fma2(v01.x, W01, mul2(v00.x, W00))));
    o.y = fma2(v11.y, W11, fma2(v10.y, W10, fma2(v01.y, W01, mul2(v00.y, W00))));
    return o;
}

// One CTA per (roi, py) output row: 7 px cells, 256 threads, 1 float4 lane
// each. Depth-1 software pipeline over px. NEW: warp-uniform register reuse —
// when next cell's left column equals current cell's right column
// (x0(px+1) == x1(px), uniform across the CTA since the ROI is shared),
// the two left loads are skipped and taken from registers, cutting L1
// read requests by ~12% on average (up to 43% for the smallest ROIs).
__global__ __launch_bounds__(256)
void roi_pool_kernel(const float* __restrict__ img,
                     const int*   __restrict__ rois,
                     float*       __restrict__ out)
{
    const int bid = blockIdx.x;           // roi*7 + py
    const int roi = bid / POOL;
    const int py  = bid - roi * POOL;

    const int4 r = __ldg(((const int4*)rois) + roi);   // x, y, w, h

    // Loop-invariant y-axis work (match reference fp32 arithmetic exactly)
    const float stepx = (float)r.z / (float)POOL;
    const float sy = (float)py * ((float)r.w / (float)POOL);
    const int   y0 = (int)sy;
    const float fy = sy - (float)y0;
    const int   y1 = min(y0 + 1, r.w - 1);
    const int   wm1 = r.z - 1;

    const int c = threadIdx.x;            // 0..255 float4 lane
    const ulonglong2* ibase = (const ulonglong2*)img;
    const unsigned row0 = (unsigned)((r.y + y0) * IMG_W + r.x) * 256u + c;
    const unsigned row1 = (unsigned)((r.y + y1) * IMG_W + r.x) * 256u + c;

    ulonglong2* optr = (ulonglong2*)out + ((size_t)bid * POOL) * 256 + c;

    // ---- prologue: px = 0 (sx = 0, x0 = 0, fx = 0) ----
    float fxc = 0.0f;
    unsigned prev_x1 = (unsigned)min(1, wm1);   // current cell's right column
    {
        const unsigned x1u = prev_x1 * 256u;
        ulonglong2 a00 = __ldg(ibase + row0);
        ulonglong2 a01 = __ldg(ibase + row0 + x1u);
        ulonglong2 a10 = __ldg(ibase + row1);
        ulonglong2 a11 = __ldg(ibase + row1 + x1u);

        #pragma unroll
        for (int px = 1; px < POOL; ++px) {
            const float sx  = (float)px * stepx;
            const int   x0  = (int)sx;
            const float fxn = sx - (float)x0;
            const unsigned x1n = (unsigned)min(x0 + 1, wm1);
            const unsigned u0 = (unsigned)x0 * 256u;
            const unsigned u1 = x1n * 256u;
            const bool reuse = ((unsigned)x0 == prev_x1);   // warp-uniform

            // prefetch next cell's pixels; left column may come from regs
            ulonglong2 b00, b10;
            if (reuse) { b00 = a01; b10 = a11; }
            else       { b00 = __ldg(ibase + row0 + u0);
                         b10 = __ldg(ibase + row1 + u0); }
            const ulonglong2 b01 = __ldg(ibase + row0 + u1);
            const ulonglong2 b11 = __ldg(ibase + row1 + u1);

            stg_cs(optr, blend2(a00, a01, a10, a11, fxc, fy));
            optr += 256;

            a00 = b00; a01 = b01; a10 = b10; a11 = b11;
            fxc = fxn;
            prev_x1 = x1n;
        }

        // ---- epilogue: px = 6 ----
        stg_cs(optr, blend2(a00, a01, a10, a11, fxc, fy));
    }
}

extern "C" void kernel_launch(void* const* d_in, const int* in_sizes, int n_in,
                              void* d_out, int out_size)
{
    const float* img  = (const float*)d_in[0];
    const int*   rois = (const int*)d_in[1];
    float*       out  = (float*)d_out;

    const int grid = NROIS * POOL;        // 3584 CTAs, one per (roi, py)
    roi_pool_kernel<<<grid, 256>>>(img, rois, out);
}